// round 11
// baseline (speedup 1.0000x reference)
#include <cuda_runtime.h>
#include <cuda_fp16.h>
#include <math.h>
#include <stdint.h>

#define DM    1024
#define FFN_  4096
#define NE    8
#define TMAX  8192
#define GROWS (2*TMAX + 128)

// ---------------- device scratch ----------------
__device__ int    g_counts[NE];
__device__ int    g_base[NE];
__device__ int    g_tok[NE][TMAX];
__device__ float  g_gate[NE][TMAX];
__device__ __half g_Xgh[(size_t)GROWS * DM];
__device__ __half g_Hh[(size_t)GROWS * FFN_];
__device__ __half g_w1h[(size_t)NE * DM * FFN_];
__device__ __half g_w2h[(size_t)NE * FFN_ * DM];

// ---------------- helpers ----------------
__device__ __forceinline__ uint32_t smem_u32(const void* p) {
    uint32_t a;
    asm("{ .reg .u64 t; cvta.to.shared.u64 t, %1; cvt.u32.u64 %0, t; }" : "=r"(a) : "l"(p));
    return a;
}
__device__ __forceinline__ float gelu_exact(float v) {
    return 0.5f * v * (1.f + erff(v * 0.7071067811865476f));
}

#define CP_ASYNC16(dst, src) \
    asm volatile("cp.async.cg.shared.global [%0], [%1], 16;" :: "r"(dst), "l"(src) : "memory")
#define CP_COMMIT()  asm volatile("cp.async.commit_group;" ::: "memory")
#define CP_WAIT2()   asm volatile("cp.async.wait_group 2;" ::: "memory")

#define LDMATRIX_X4(r0,r1,r2,r3, addr) \
    asm volatile("ldmatrix.sync.aligned.m8n8.x4.shared.b16 {%0,%1,%2,%3}, [%4];" \
        : "=r"(r0), "=r"(r1), "=r"(r2), "=r"(r3) : "r"(addr))
#define LDMATRIX_X4_T(r0,r1,r2,r3, addr) \
    asm volatile("ldmatrix.sync.aligned.m8n8.x4.trans.shared.b16 {%0,%1,%2,%3}, [%4];" \
        : "=r"(r0), "=r"(r1), "=r"(r2), "=r"(r3) : "r"(addr))

// fp16-accumulate MMA: D,C are 2 regs of packed half2
#define MMA_F16ACC(c0, c1, a, b0, b1) \
    asm volatile("mma.sync.aligned.m16n8k16.row.col.f16.f16.f16.f16 " \
        "{%0,%1}, {%2,%3,%4,%5}, {%6,%7}, {%0,%1};" \
        : "+r"(c0), "+r"(c1) \
        : "r"((a)[0]), "r"((a)[1]), "r"((a)[2]), "r"((a)[3]), "r"(b0), "r"(b1))

// ---------------- routing ----------------
__global__ void init_kernel() { if (threadIdx.x < NE) g_counts[threadIdx.x] = 0; }

__global__ void base_kernel() {
    if (threadIdx.x == 0) {
        int s = 0;
        #pragma unroll
        for (int e = 0; e < NE; e++) { g_base[e] = s; s += g_counts[e]; }
    }
}

__global__ void route_kernel(const float* __restrict__ x,
                             const float* __restrict__ gw,
                             const float* __restrict__ gb, int T) {
    int warp = (blockIdx.x * blockDim.x + threadIdx.x) >> 5;
    int lane = threadIdx.x & 31;
    if (warp >= T) return;
    const float* xr = x + (size_t)warp * DM;
    float acc[NE];
    #pragma unroll
    for (int e = 0; e < NE; e++) acc[e] = 0.f;
    for (int d = lane; d < DM; d += 32) {
        float xv = xr[d];
        const float4* g4 = (const float4*)(gw + (size_t)d * NE);
        float4 a = g4[0], b = g4[1];
        acc[0] += xv*a.x; acc[1] += xv*a.y; acc[2] += xv*a.z; acc[3] += xv*a.w;
        acc[4] += xv*b.x; acc[5] += xv*b.y; acc[6] += xv*b.z; acc[7] += xv*b.w;
    }
    #pragma unroll
    for (int e = 0; e < NE; e++)
        #pragma unroll
        for (int o = 16; o > 0; o >>= 1) acc[e] += __shfl_xor_sync(0xFFFFFFFFu, acc[e], o);
    if (lane == 0) {
        float v[NE];
        #pragma unroll
        for (int e = 0; e < NE; e++) v[e] = acc[e] + gb[e];
        int i1 = 0;
        #pragma unroll
        for (int e = 1; e < NE; e++) if (v[e] > v[i1]) i1 = e;
        int i2 = (i1 == 0) ? 1 : 0;
        #pragma unroll
        for (int e = 0; e < NE; e++) if (e != i1 && v[e] > v[i2]) i2 = e;
        float e2 = expf(v[i2] - v[i1]);
        float s = 1.f + e2;
        int s1 = atomicAdd(&g_counts[i1], 1);
        g_tok[i1][s1] = warp; g_gate[i1][s1] = 1.f / s;
        int s2 = atomicAdd(&g_counts[i2], 1);
        g_tok[i2][s2] = warp; g_gate[i2][s2] = e2 / s;
    }
}

__global__ void gather_kernel(const float* __restrict__ x) {
    int e = blockIdx.y;
    int slot = blockIdx.x * 2 + (threadIdx.x >> 7);
    if (slot >= g_counts[e]) return;
    int tok = g_tok[e][slot];
    int row = g_base[e] + slot;
    int lane = threadIdx.x & 127;
    const float4* s = (const float4*)(x + (size_t)tok * DM);
    uint2* d = (uint2*)(g_Xgh + (size_t)row * DM);
    #pragma unroll
    for (int i = 0; i < 2; i++) {
        float4 v = s[lane + i * 128];
        __half2 h0 = __floats2half2_rn(v.x, v.y);
        __half2 h1 = __floats2half2_rn(v.z, v.w);
        uint2 o;
        o.x = *reinterpret_cast<uint32_t*>(&h0);
        o.y = *reinterpret_cast<uint32_t*>(&h1);
        d[lane + i * 128] = o;
    }
}

// fp32 -> fp16 conversion of BOTH weight tensors in one launch
__global__ void conv_half_kernel(const float4* __restrict__ s1, uint4* __restrict__ d1,
                                 const float4* __restrict__ s2, uint4* __restrict__ d2, int n8) {
    int i = blockIdx.x * blockDim.x + threadIdx.x;
    if (i >= 2 * n8) return;
    const float4* s = (i < n8) ? s1 : s2;
    uint4* d = (i < n8) ? d1 : d2;
    int j = (i < n8) ? i : (i - n8);
    float4 v0 = s[j * 2], v1 = s[j * 2 + 1];
    __half2 h0 = __floats2half2_rn(v0.x, v0.y);
    __half2 h1 = __floats2half2_rn(v0.z, v0.w);
    __half2 h2 = __floats2half2_rn(v1.x, v1.y);
    __half2 h3 = __floats2half2_rn(v1.z, v1.w);
    uint4 o;
    o.x = *reinterpret_cast<uint32_t*>(&h0);
    o.y = *reinterpret_cast<uint32_t*>(&h1);
    o.z = *reinterpret_cast<uint32_t*>(&h2);
    o.w = *reinterpret_cast<uint32_t*>(&h3);
    d[j] = o;
}

// ---------------- fp16 mma grouped GEMM (f16 accum + chunk promotion) ----------------
// CTA 128x128, 256 threads = 8 warps (2x4), warp tile 64x32, k-chunk 32.
// smem (halves): A [128][40], B [32][136], 4-stage pipeline.
#define ASTRH 40
#define BSTRH 136
#define ABUFB (128 * ASTRH * 2)
#define BBUFB (32 * BSTRH * 2)
#define BUFB  (ABUFB + BBUFB)
#define NSTAGE 4
#define SMEM_DYN (NSTAGE * BUFB)

template<int KDIM, int NDIM, bool GELU_OUT>
__global__ void __launch_bounds__(256, 1)
gemm_mma(const __half* __restrict__ Bmat, const float* __restrict__ bias,
         float* __restrict__ outp) {
    const int e = blockIdx.z;
    const int count = g_counts[e];
    const int m0 = blockIdx.x * 128;
    if (m0 >= count) return;
    const int base = g_base[e];
    const int n0 = blockIdx.y * 128;

    extern __shared__ char smraw[];
    const uint32_t su = smem_u32(smraw);

    const int tid  = threadIdx.x;
    const int wid  = tid >> 5;
    const int lane = tid & 31;
    const int g    = lane >> 2;
    const int tg   = lane & 3;
    const int wr   = wid & 1;
    const int wc   = wid >> 1;

    const __half* Asrc = (GELU_OUT ? g_Xgh : g_Hh) + (size_t)(base + m0) * KDIM;
    const __half* Bsrc = Bmat + (size_t)e * KDIM * NDIM + n0;

    const int am = tid >> 1;
    const int ac = (tid & 1) * 2;
    const int bk = tid >> 3;
    const int bc = (tid & 7) * 2;

    const int lane_r  = (lane & 7) + ((lane >> 3) & 1) * 8;
    const int lane_k8 = (lane >> 4) * 16;

    float c[4][4][4];
    #pragma unroll
    for (int i = 0; i < 4; i++)
        #pragma unroll
        for (int j = 0; j < 4; j++)
            #pragma unroll
            for (int k = 0; k < 4; k++) c[i][j][k] = 0.f;

    const int KC = KDIM / 32;

    #define LOAD_TILES(kc_, buf_) do { \
        uint32_t sa = su + (buf_) * BUFB; \
        uint32_t sb = sa + ABUFB; \
        const __half* asp = Asrc + (size_t)am * KDIM + (kc_) * 32; \
        _Pragma("unroll") \
        for (int j = 0; j < 2; j++) \
            CP_ASYNC16(sa + (uint32_t)(am * 80 + (ac + j) * 16), asp + (ac + j) * 8); \
        const __half* bsp = Bsrc + (size_t)((kc_) * 32 + bk) * NDIM; \
        _Pragma("unroll") \
        for (int j = 0; j < 2; j++) \
            CP_ASYNC16(sb + (uint32_t)(bk * 272 + (bc + j) * 16), bsp + (bc + j) * 8); \
    } while (0)

    LOAD_TILES(0, 0); CP_COMMIT();
    LOAD_TILES(1, 1); CP_COMMIT();
    LOAD_TILES(2, 2); CP_COMMIT();

    for (int kc = 0; kc < KC; kc++) {
        CP_WAIT2();
        __syncthreads();
        if (kc + 3 < KC) LOAD_TILES(kc + 3, (kc + 3) & 3);
        CP_COMMIT();

        const uint32_t sa = su + (kc & 3) * BUFB;
        const uint32_t sb = sa + ABUFB;
        const uint32_t a_base = sa + (uint32_t)((wr * 64 + lane_r) * 80) + lane_k8;
        const uint32_t b_base = sb + (uint32_t)(lane_r * 272 + wc * 64) + lane_k8;

        // fp16 chunk accumulators (zeroed each chunk)
        uint32_t ch[4][4][2];
        #pragma unroll
        for (int mf = 0; mf < 4; mf++)
            #pragma unroll
            for (int nf = 0; nf < 4; nf++) { ch[mf][nf][0] = 0u; ch[mf][nf][1] = 0u; }

        #pragma unroll
        for (int ks = 0; ks < 2; ks++) {
            uint32_t a[4][4];
            #pragma unroll
            for (int mf = 0; mf < 4; mf++)
                LDMATRIX_X4(a[mf][0], a[mf][1], a[mf][2], a[mf][3],
                            a_base + mf * 1280 + ks * 32);
            uint32_t b[4][2];
            #pragma unroll
            for (int np = 0; np < 2; np++) {
                uint32_t r0, r1, r2, r3;
                LDMATRIX_X4_T(r0, r1, r2, r3, b_base + ks * 4352 + np * 32);
                b[np * 2 + 0][0] = r0; b[np * 2 + 0][1] = r1;
                b[np * 2 + 1][0] = r2; b[np * 2 + 1][1] = r3;
            }
            #pragma unroll
            for (int mf = 0; mf < 4; mf++)
                #pragma unroll
                for (int nf = 0; nf < 4; nf++)
                    MMA_F16ACC(ch[mf][nf][0], ch[mf][nf][1], a[mf], b[nf][0], b[nf][1]);
        }

        // promote chunk sums to fp32
        #pragma unroll
        for (int mf = 0; mf < 4; mf++)
            #pragma unroll
            for (int nf = 0; nf < 4; nf++) {
                float2 lo = __half22float2(*reinterpret_cast<__half2*>(&ch[mf][nf][0]));
                float2 hi = __half22float2(*reinterpret_cast<__half2*>(&ch[mf][nf][1]));
                c[mf][nf][0] += lo.x;
                c[mf][nf][1] += lo.y;
                c[mf][nf][2] += hi.x;
                c[mf][nf][3] += hi.y;
            }
    }

    // -------- epilogue --------
    #pragma unroll
    for (int mf = 0; mf < 4; mf++) {
        #pragma unroll
        for (int half_ = 0; half_ < 2; half_++) {
            int rl = wr * 64 + mf * 16 + g + half_ * 8;
            int m = m0 + rl;
            if (m >= count) continue;
            if (GELU_OUT) {
                __half* hrow = g_Hh + (size_t)(base + m) * FFN_;
                #pragma unroll
                for (int nf = 0; nf < 4; nf++) {
                    int col = n0 + wc * 32 + nf * 8 + 2 * tg;
                    float2 bb = *(const float2*)(bias + (size_t)e * NDIM + col);
                    __half2 hv = __floats2half2_rn(
                        gelu_exact(c[mf][nf][half_ * 2 + 0] + bb.x),
                        gelu_exact(c[mf][nf][half_ * 2 + 1] + bb.y));
                    *reinterpret_cast<__half2*>(hrow + col) = hv;
                }
            } else {
                int tok = g_tok[e][m];
                float gt = g_gate[e][m];
                float* orow = outp + (size_t)tok * DM;
                #pragma unroll
                for (int nf = 0; nf < 4; nf++) {
                    int col = n0 + wc * 32 + nf * 8 + 2 * tg;
                    float2 bb = *(const float2*)(bias + (size_t)e * NDIM + col);
                    atomicAdd(orow + col + 0, gt * (c[mf][nf][half_ * 2 + 0] + bb.x));
                    atomicAdd(orow + col + 1, gt * (c[mf][nf][half_ * 2 + 1] + bb.y));
                }
            }
        }
    }
}

// ---------------- launch ----------------
extern "C" void kernel_launch(void* const* d_in, const int* in_sizes, int n_in,
                              void* d_out, int out_size) {
    const float* x  = (const float*)d_in[0];
    const float* gw = (const float*)d_in[1];
    const float* gb = (const float*)d_in[2];
    const float* w1 = (const float*)d_in[3];
    const float* b1 = (const float*)d_in[4];
    const float* w2 = (const float*)d_in[5];
    const float* b2 = (const float*)d_in[6];
    float* out = (float*)d_out;
    const int T = in_sizes[0] / DM;

    __half* w1h; cudaGetSymbolAddress((void**)&w1h, g_w1h);
    __half* w2h; cudaGetSymbolAddress((void**)&w2h, g_w2h);

    static int attr_done = 0;
    if (!attr_done) {
        cudaFuncSetAttribute(gemm_mma<DM, FFN_, true>,
                             cudaFuncAttributeMaxDynamicSharedMemorySize, SMEM_DYN);
        cudaFuncSetAttribute(gemm_mma<FFN_, DM, false>,
                             cudaFuncAttributeMaxDynamicSharedMemorySize, SMEM_DYN);
        attr_done = 1;
    }

    init_kernel<<<1, 32>>>();
    route_kernel<<<(T + 7) / 8, 256>>>(x, gw, gb, T);
    base_kernel<<<1, 32>>>();
    gather_kernel<<<dim3((T + 1) / 2, NE), 256>>>(x);

    const int n8 = NE * DM * FFN_ / 8;
    conv_half_kernel<<<(2 * n8 + 255) / 256, 256>>>(
        (const float4*)w1, (uint4*)w1h, (const float4*)w2, (uint4*)w2h, n8);

    cudaMemsetAsync(d_out, 0, (size_t)out_size * sizeof(float), 0);

    gemm_mma<DM, FFN_, true><<<dim3(T / 128, FFN_ / 128, NE), 256, SMEM_DYN>>>(w1h, b1, nullptr);
    gemm_mma<FFN_, DM, false><<<dim3(T / 128, DM / 128, NE), 256, SMEM_DYN>>>(w2h, b2, out);
}

// round 12
// speedup vs baseline: 1.2746x; 1.2746x over previous
#include <cuda_runtime.h>
#include <cuda_fp16.h>
#include <math.h>
#include <stdint.h>

#define DM    1024
#define FFN_  4096
#define NE    8
#define TMAX  8192
#define GROWS (2*TMAX + 128)

// ---------------- device scratch ----------------
__device__ int    g_counts[NE];
__device__ int    g_base[NE];
__device__ int    g_tok[NE][TMAX];
__device__ float  g_gate[NE][TMAX];
__device__ __half g_Xh[(size_t)TMAX * DM];      // token-order fp16 x
__device__ __half g_Hh[(size_t)GROWS * FFN_];   // grouped gelu output

// ---------------- helpers ----------------
__device__ __forceinline__ uint32_t smem_u32(const void* p) {
    uint32_t a;
    asm("{ .reg .u64 t; cvta.to.shared.u64 t, %1; cvt.u32.u64 %0, t; }" : "=r"(a) : "l"(p));
    return a;
}
__device__ __forceinline__ float gelu_exact(float v) {
    return 0.5f * v * (1.f + erff(v * 0.7071067811865476f));
}

#define CP_ASYNC16(dst, src) \
    asm volatile("cp.async.cg.shared.global [%0], [%1], 16;" :: "r"(dst), "l"(src) : "memory")
#define CP_COMMIT()  asm volatile("cp.async.commit_group;" ::: "memory")
#define CP_WAIT2()   asm volatile("cp.async.wait_group 2;" ::: "memory")

#define LDMATRIX_X4(r0,r1,r2,r3, addr) \
    asm volatile("ldmatrix.sync.aligned.m8n8.x4.shared.b16 {%0,%1,%2,%3}, [%4];" \
        : "=r"(r0), "=r"(r1), "=r"(r2), "=r"(r3) : "r"(addr))
#define LDMATRIX_X4_T(r0,r1,r2,r3, addr) \
    asm volatile("ldmatrix.sync.aligned.m8n8.x4.trans.shared.b16 {%0,%1,%2,%3}, [%4];" \
        : "=r"(r0), "=r"(r1), "=r"(r2), "=r"(r3) : "r"(addr))

#define MMA_F16(c, a, b0, b1) \
    asm volatile("mma.sync.aligned.m16n8k16.row.col.f32.f16.f16.f32 " \
        "{%0,%1,%2,%3}, {%4,%5,%6,%7}, {%8,%9}, {%0,%1,%2,%3};" \
        : "+f"((c)[0]), "+f"((c)[1]), "+f"((c)[2]), "+f"((c)[3]) \
        : "r"((a)[0]), "r"((a)[1]), "r"((a)[2]), "r"((a)[3]), "r"(b0), "r"(b1))

// ---------------- routing ----------------
__global__ void init_kernel() { if (threadIdx.x < NE) g_counts[threadIdx.x] = 0; }

__global__ void base_kernel() {
    if (threadIdx.x == 0) {
        int s = 0;
        #pragma unroll
        for (int e = 0; e < NE; e++) { g_base[e] = s; s += g_counts[e]; }
    }
}

__global__ void route_kernel(const float* __restrict__ x,
                             const float* __restrict__ gw,
                             const float* __restrict__ gb, int T) {
    int warp = (blockIdx.x * blockDim.x + threadIdx.x) >> 5;
    int lane = threadIdx.x & 31;
    if (warp >= T) return;
    const float* xr = x + (size_t)warp * DM;
    float acc[NE];
    #pragma unroll
    for (int e = 0; e < NE; e++) acc[e] = 0.f;
    for (int d = lane; d < DM; d += 32) {
        float xv = xr[d];
        const float4* g4 = (const float4*)(gw + (size_t)d * NE);
        float4 a = g4[0], b = g4[1];
        acc[0] += xv*a.x; acc[1] += xv*a.y; acc[2] += xv*a.z; acc[3] += xv*a.w;
        acc[4] += xv*b.x; acc[5] += xv*b.y; acc[6] += xv*b.z; acc[7] += xv*b.w;
    }
    #pragma unroll
    for (int e = 0; e < NE; e++)
        #pragma unroll
        for (int o = 16; o > 0; o >>= 1) acc[e] += __shfl_xor_sync(0xFFFFFFFFu, acc[e], o);
    if (lane == 0) {
        float v[NE];
        #pragma unroll
        for (int e = 0; e < NE; e++) v[e] = acc[e] + gb[e];
        int i1 = 0;
        #pragma unroll
        for (int e = 1; e < NE; e++) if (v[e] > v[i1]) i1 = e;
        int i2 = (i1 == 0) ? 1 : 0;
        #pragma unroll
        for (int e = 0; e < NE; e++) if (e != i1 && v[e] > v[i2]) i2 = e;
        float e2 = expf(v[i2] - v[i1]);
        float s = 1.f + e2;
        int s1 = atomicAdd(&g_counts[i1], 1);
        g_tok[i1][s1] = warp; g_gate[i1][s1] = 1.f / s;
        int s2 = atomicAdd(&g_counts[i2], 1);
        g_tok[i2][s2] = warp; g_gate[i2][s2] = e2 / s;
    }
}

// token-order fp32 -> fp16 conversion of x
__global__ void convx_kernel(const float4* __restrict__ src, uint2* __restrict__ dst, int n4) {
    int i = blockIdx.x * blockDim.x + threadIdx.x;
    if (i >= n4) return;
    float4 v = src[i];
    __half2 h0 = __floats2half2_rn(v.x, v.y);
    __half2 h1 = __floats2half2_rn(v.z, v.w);
    uint2 o;
    o.x = *reinterpret_cast<uint32_t*>(&h0);
    o.y = *reinterpret_cast<uint32_t*>(&h1);
    dst[i] = o;
}

// ---------------- fp16 mma grouped GEMM ----------------
// CTA 128x128, 256 threads = 8 warps (2x4), warp tile 64x32, k-chunk 32.
// A: fp16 source, 4-stage cp.async. B: fp32 weights, LDG->cvt->STS double buffer.
#define ASTRH 40
#define BSTRH 136
#define ABUFB (128 * ASTRH * 2)          // 10240 B per stage
#define BBUFB (32 * BSTRH * 2)           // 8704 B per buffer
#define NSTAGE 4
#define SMEM_DYN (NSTAGE * ABUFB + 2 * BBUFB)   // 58368 B

template<int KDIM, int NDIM, bool GELU_OUT>
__global__ void __launch_bounds__(256, 2)
gemm_mma(const float* __restrict__ Bmat, const float* __restrict__ bias,
         float* __restrict__ outp) {
    const int e = blockIdx.z;
    const int count = g_counts[e];
    const int m0 = blockIdx.x * 128;
    if (m0 >= count) return;
    const int base = g_base[e];
    const int n0 = blockIdx.y * 128;

    extern __shared__ char smraw[];
    const uint32_t su = smem_u32(smraw);
    const uint32_t sbB = su + NSTAGE * ABUFB;    // B double buffer region

    const int tid  = threadIdx.x;
    const int wid  = tid >> 5;
    const int lane = tid & 31;
    const int g    = lane >> 2;
    const int tg   = lane & 3;
    const int wr   = wid & 1;
    const int wc   = wid >> 1;

    // ---- A source pointer (per loader row) ----
    const int am = tid >> 1;                 // 0..127
    const int ac = (tid & 1) * 2;            // 16B-chunk pair
    const __half* arow_ptr;
    if (GELU_OUT) {
        int arow = m0 + am;
        int tok = (arow < count) ? g_tok[e][arow] : g_tok[e][count - 1];
        arow_ptr = g_Xh + (size_t)tok * KDIM;
    } else {
        int arow = m0 + am;
        if (arow >= count) arow = count - 1;
        arow_ptr = g_Hh + (size_t)(base + arow) * KDIM;
    }

    // ---- B loader mapping (fp32) ----
    const int bk  = tid >> 3;                // 0..31 (k row)
    const int bcf = (tid & 7) * 16;          // float col offset (16 floats/thread)
    const float* Bsrc = Bmat + (size_t)e * KDIM * NDIM + n0;

    const int lane_r  = (lane & 7) + ((lane >> 3) & 1) * 8;
    const int lane_k8 = (lane >> 4) * 16;

    float c[4][4][4];
    #pragma unroll
    for (int i = 0; i < 4; i++)
        #pragma unroll
        for (int j = 0; j < 4; j++)
            #pragma unroll
            for (int k = 0; k < 4; k++) c[i][j][k] = 0.f;

    const int KC = KDIM / 32;

    float4 br0, br1, br2, br3;   // B register stage (16 floats)

    #define LOAD_A(kc_, buf_) do { \
        uint32_t sa = su + (buf_) * ABUFB; \
        const __half* asp = arow_ptr + (kc_) * 32; \
        _Pragma("unroll") \
        for (int j = 0; j < 2; j++) \
            CP_ASYNC16(sa + (uint32_t)(am * 80 + (ac + j) * 16), asp + (ac + j) * 8); \
    } while (0)

    #define LDG_B(kc_) do { if ((kc_) < KC) { \
        const float* bp = Bsrc + (size_t)((kc_) * 32 + bk) * NDIM + bcf; \
        br0 = *(const float4*)(bp + 0); \
        br1 = *(const float4*)(bp + 4); \
        br2 = *(const float4*)(bp + 8); \
        br3 = *(const float4*)(bp + 12); \
    } } while (0)

    #define STS_B(kc_) do { if ((kc_) < KC) { \
        uint32_t sb = sbB + ((kc_) & 1) * BBUFB + (uint32_t)(bk * 272 + bcf * 2); \
        __half2 q0 = __floats2half2_rn(br0.x, br0.y); \
        __half2 q1 = __floats2half2_rn(br0.z, br0.w); \
        __half2 q2 = __floats2half2_rn(br1.x, br1.y); \
        __half2 q3 = __floats2half2_rn(br1.z, br1.w); \
        __half2 q4 = __floats2half2_rn(br2.x, br2.y); \
        __half2 q5 = __floats2half2_rn(br2.z, br2.w); \
        __half2 q6 = __floats2half2_rn(br3.x, br3.y); \
        __half2 q7 = __floats2half2_rn(br3.z, br3.w); \
        asm volatile("st.shared.v4.b32 [%0], {%1,%2,%3,%4};" :: "r"(sb), \
            "r"(*(uint32_t*)&q0), "r"(*(uint32_t*)&q1), "r"(*(uint32_t*)&q2), "r"(*(uint32_t*)&q3) : "memory"); \
        asm volatile("st.shared.v4.b32 [%0], {%1,%2,%3,%4};" :: "r"(sb + 16), \
            "r"(*(uint32_t*)&q4), "r"(*(uint32_t*)&q5), "r"(*(uint32_t*)&q6), "r"(*(uint32_t*)&q7) : "memory"); \
    } } while (0)

    // prologue
    LDG_B(0);
    LOAD_A(0, 0); CP_COMMIT();
    LOAD_A(1, 1); CP_COMMIT();
    LOAD_A(2, 2); CP_COMMIT();
    STS_B(0);
    LDG_B(1);

    for (int kc = 0; kc < KC; kc++) {
        CP_WAIT2();
        __syncthreads();
        STS_B(kc + 1);          // regs hold B(kc+1), write to buf[(kc+1)&1]
        LDG_B(kc + 2);          // prefetch next into regs
        if (kc + 3 < KC) LOAD_A(kc + 3, (kc + 3) & 3);
        CP_COMMIT();

        const uint32_t sa = su + (kc & 3) * ABUFB;
        const uint32_t sb = sbB + (kc & 1) * BBUFB;
        const uint32_t a_base = sa + (uint32_t)((wr * 64 + lane_r) * 80) + lane_k8;
        const uint32_t b_base = sb + (uint32_t)(lane_r * 272 + wc * 64) + lane_k8;

        #pragma unroll
        for (int ks = 0; ks < 2; ks++) {
            uint32_t a[4][4];
            #pragma unroll
            for (int mf = 0; mf < 4; mf++)
                LDMATRIX_X4(a[mf][0], a[mf][1], a[mf][2], a[mf][3],
                            a_base + mf * 1280 + ks * 32);
            uint32_t b[4][2];
            #pragma unroll
            for (int np = 0; np < 2; np++) {
                uint32_t r0, r1, r2, r3;
                LDMATRIX_X4_T(r0, r1, r2, r3, b_base + ks * 4352 + np * 32);
                b[np * 2 + 0][0] = r0; b[np * 2 + 0][1] = r1;
                b[np * 2 + 1][0] = r2; b[np * 2 + 1][1] = r3;
            }
            #pragma unroll
            for (int mf = 0; mf < 4; mf++)
                #pragma unroll
                for (int nf = 0; nf < 4; nf++)
                    MMA_F16(c[mf][nf], a[mf], b[nf][0], b[nf][1]);
        }
    }

    // -------- epilogue --------
    #pragma unroll
    for (int mf = 0; mf < 4; mf++) {
        #pragma unroll
        for (int half_ = 0; half_ < 2; half_++) {
            int rl = wr * 64 + mf * 16 + g + half_ * 8;
            int m = m0 + rl;
            if (m >= count) continue;
            if (GELU_OUT) {
                __half* hrow = g_Hh + (size_t)(base + m) * FFN_;
                #pragma unroll
                for (int nf = 0; nf < 4; nf++) {
                    int col = n0 + wc * 32 + nf * 8 + 2 * tg;
                    float2 bb = *(const float2*)(bias + (size_t)e * NDIM + col);
                    __half2 hv = __floats2half2_rn(
                        gelu_exact(c[mf][nf][half_ * 2 + 0] + bb.x),
                        gelu_exact(c[mf][nf][half_ * 2 + 1] + bb.y));
                    *reinterpret_cast<__half2*>(hrow + col) = hv;
                }
            } else {
                int tok = g_tok[e][m];
                float gt = g_gate[e][m];
                float* orow = outp + (size_t)tok * DM;
                #pragma unroll
                for (int nf = 0; nf < 4; nf++) {
                    int col = n0 + wc * 32 + nf * 8 + 2 * tg;
                    float2 bb = *(const float2*)(bias + (size_t)e * NDIM + col);
                    atomicAdd(orow + col + 0, gt * (c[mf][nf][half_ * 2 + 0] + bb.x));
                    atomicAdd(orow + col + 1, gt * (c[mf][nf][half_ * 2 + 1] + bb.y));
                }
            }
        }
    }
}

// ---------------- launch ----------------
extern "C" void kernel_launch(void* const* d_in, const int* in_sizes, int n_in,
                              void* d_out, int out_size) {
    const float* x  = (const float*)d_in[0];
    const float* gw = (const float*)d_in[1];
    const float* gb = (const float*)d_in[2];
    const float* w1 = (const float*)d_in[3];
    const float* b1 = (const float*)d_in[4];
    const float* w2 = (const float*)d_in[5];
    const float* b2 = (const float*)d_in[6];
    float* out = (float*)d_out;
    const int T = in_sizes[0] / DM;

    __half* xh; cudaGetSymbolAddress((void**)&xh, g_Xh);

    static int attr_done = 0;
    if (!attr_done) {
        cudaFuncSetAttribute(gemm_mma<DM, FFN_, true>,
                             cudaFuncAttributeMaxDynamicSharedMemorySize, SMEM_DYN);
        cudaFuncSetAttribute(gemm_mma<FFN_, DM, false>,
                             cudaFuncAttributeMaxDynamicSharedMemorySize, SMEM_DYN);
        attr_done = 1;
    }

    init_kernel<<<1, 32>>>();
    route_kernel<<<(T + 7) / 8, 256>>>(x, gw, gb, T);
    base_kernel<<<1, 32>>>();

    const int n4 = T * DM / 4;
    convx_kernel<<<(n4 + 255) / 256, 256>>>((const float4*)x, (uint2*)xh, n4);

    cudaMemsetAsync(d_out, 0, (size_t)out_size * sizeof(float), 0);

    gemm_mma<DM, FFN_, true><<<dim3(T / 128, FFN_ / 128, NE), 256, SMEM_DYN>>>(w1, b1, nullptr);
    gemm_mma<FFN_, DM, false><<<dim3(T / 128, DM / 128, NE), 256, SMEM_DYN>>>(w2, b2, out);
}

// round 13
// speedup vs baseline: 1.5315x; 1.2016x over previous
#include <cuda_runtime.h>
#include <cuda_fp16.h>
#include <math.h>
#include <stdint.h>

#define DM    1024
#define FFN_  4096
#define NE    8
#define TMAX  8192
#define GROWS (2*TMAX + 128)

// ---------------- device scratch ----------------
__device__ int    g_counts[NE];
__device__ int    g_base[NE];
__device__ int    g_tok[NE][TMAX];
__device__ float  g_gate[NE][TMAX];
__device__ __half g_Xgh[(size_t)GROWS * DM];
__device__ __half g_Hh[(size_t)GROWS * FFN_];
__device__ __half g_w1h[(size_t)NE * DM * FFN_];
__device__ __half g_w2h[(size_t)NE * FFN_ * DM];

// ---------------- helpers ----------------
__device__ __forceinline__ uint32_t smem_u32(const void* p) {
    uint32_t a;
    asm("{ .reg .u64 t; cvta.to.shared.u64 t, %1; cvt.u32.u64 %0, t; }" : "=r"(a) : "l"(p));
    return a;
}
__device__ __forceinline__ float gelu_exact(float v) {
    return 0.5f * v * (1.f + erff(v * 0.7071067811865476f));
}

#define CP_ASYNC16(dst, src) \
    asm volatile("cp.async.cg.shared.global [%0], [%1], 16;" :: "r"(dst), "l"(src) : "memory")
#define CP_COMMIT()  asm volatile("cp.async.commit_group;" ::: "memory")
#define CP_WAIT2()   asm volatile("cp.async.wait_group 2;" ::: "memory")

#define LDMATRIX_X4(r0,r1,r2,r3, addr) \
    asm volatile("ldmatrix.sync.aligned.m8n8.x4.shared.b16 {%0,%1,%2,%3}, [%4];" \
        : "=r"(r0), "=r"(r1), "=r"(r2), "=r"(r3) : "r"(addr))
#define LDMATRIX_X4_T(r0,r1,r2,r3, addr) \
    asm volatile("ldmatrix.sync.aligned.m8n8.x4.trans.shared.b16 {%0,%1,%2,%3}, [%4];" \
        : "=r"(r0), "=r"(r1), "=r"(r2), "=r"(r3) : "r"(addr))

#define MMA_F16(c, a, b0, b1) \
    asm volatile("mma.sync.aligned.m16n8k16.row.col.f32.f16.f16.f32 " \
        "{%0,%1,%2,%3}, {%4,%5,%6,%7}, {%8,%9}, {%0,%1,%2,%3};" \
        : "+f"((c)[0]), "+f"((c)[1]), "+f"((c)[2]), "+f"((c)[3]) \
        : "r"((a)[0]), "r"((a)[1]), "r"((a)[2]), "r"((a)[3]), "r"(b0), "r"(b1))

// ---------------- routing ----------------
__global__ void init_kernel() { if (threadIdx.x < NE) g_counts[threadIdx.x] = 0; }

__global__ void base_kernel() {
    if (threadIdx.x == 0) {
        int s = 0;
        #pragma unroll
        for (int e = 0; e < NE; e++) { g_base[e] = s; s += g_counts[e]; }
    }
}

__global__ void route_kernel(const float* __restrict__ x,
                             const float* __restrict__ gw,
                             const float* __restrict__ gb, int T) {
    int warp = (blockIdx.x * blockDim.x + threadIdx.x) >> 5;
    int lane = threadIdx.x & 31;
    if (warp >= T) return;
    const float* xr = x + (size_t)warp * DM;
    float acc[NE];
    #pragma unroll
    for (int e = 0; e < NE; e++) acc[e] = 0.f;
    for (int d = lane; d < DM; d += 32) {
        float xv = xr[d];
        const float4* g4 = (const float4*)(gw + (size_t)d * NE);
        float4 a = g4[0], b = g4[1];
        acc[0] += xv*a.x; acc[1] += xv*a.y; acc[2] += xv*a.z; acc[3] += xv*a.w;
        acc[4] += xv*b.x; acc[5] += xv*b.y; acc[6] += xv*b.z; acc[7] += xv*b.w;
    }
    #pragma unroll
    for (int e = 0; e < NE; e++)
        #pragma unroll
        for (int o = 16; o > 0; o >>= 1) acc[e] += __shfl_xor_sync(0xFFFFFFFFu, acc[e], o);
    if (lane == 0) {
        float v[NE];
        #pragma unroll
        for (int e = 0; e < NE; e++) v[e] = acc[e] + gb[e];
        int i1 = 0;
        #pragma unroll
        for (int e = 1; e < NE; e++) if (v[e] > v[i1]) i1 = e;
        int i2 = (i1 == 0) ? 1 : 0;
        #pragma unroll
        for (int e = 0; e < NE; e++) if (e != i1 && v[e] > v[i2]) i2 = e;
        float e2 = expf(v[i2] - v[i1]);
        float s = 1.f + e2;
        int s1 = atomicAdd(&g_counts[i1], 1);
        g_tok[i1][s1] = warp; g_gate[i1][s1] = 1.f / s;
        int s2 = atomicAdd(&g_counts[i2], 1);
        g_tok[i2][s2] = warp; g_gate[i2][s2] = e2 / s;
    }
}

__global__ void gather_kernel(const float* __restrict__ x) {
    int e = blockIdx.y;
    int slot = blockIdx.x * 2 + (threadIdx.x >> 7);
    if (slot >= g_counts[e]) return;
    int tok = g_tok[e][slot];
    int row = g_base[e] + slot;
    int lane = threadIdx.x & 127;
    const float4* s = (const float4*)(x + (size_t)tok * DM);
    uint2* d = (uint2*)(g_Xgh + (size_t)row * DM);
    #pragma unroll
    for (int i = 0; i < 2; i++) {
        float4 v = s[lane + i * 128];
        __half2 h0 = __floats2half2_rn(v.x, v.y);
        __half2 h1 = __floats2half2_rn(v.z, v.w);
        uint2 o;
        o.x = *reinterpret_cast<uint32_t*>(&h0);
        o.y = *reinterpret_cast<uint32_t*>(&h1);
        d[lane + i * 128] = o;
    }
}

// fp32 -> fp16 weight conversion (8 floats / thread, 16B store)
__global__ void conv_half_kernel(const float4* __restrict__ src, uint4* __restrict__ dst, int n8) {
    int i = blockIdx.x * blockDim.x + threadIdx.x;
    if (i >= n8) return;
    float4 v0 = src[i * 2], v1 = src[i * 2 + 1];
    __half2 h0 = __floats2half2_rn(v0.x, v0.y);
    __half2 h1 = __floats2half2_rn(v0.z, v0.w);
    __half2 h2 = __floats2half2_rn(v1.x, v1.y);
    __half2 h3 = __floats2half2_rn(v1.z, v1.w);
    uint4 o;
    o.x = *reinterpret_cast<uint32_t*>(&h0);
    o.y = *reinterpret_cast<uint32_t*>(&h1);
    o.z = *reinterpret_cast<uint32_t*>(&h2);
    o.w = *reinterpret_cast<uint32_t*>(&h3);
    dst[i] = o;
}

// ---------------- fp16 mma grouped GEMM (R5 config) ----------------
// CTA 128x128, 256 threads = 8 warps (2x4), warp tile 64x32, k-chunk 32.
// smem (halves): A [128][40], B [32][136], 4-stage pipeline.
#define ASTRH 40
#define BSTRH 136
#define ABUFB (128 * ASTRH * 2)
#define BBUFB (32 * BSTRH * 2)
#define BUFB  (ABUFB + BBUFB)
#define NSTAGE 4
#define SMEM_DYN (NSTAGE * BUFB)

template<int KDIM, int NDIM, bool GELU_OUT>
__global__ void __launch_bounds__(256, 2)
gemm_mma(const __half* __restrict__ Bmat, const float* __restrict__ bias,
         float* __restrict__ outp) {
    const int e = blockIdx.z;
    const int count = g_counts[e];
    const int m0 = blockIdx.x * 128;
    if (m0 >= count) return;
    const int base = g_base[e];
    const int n0 = blockIdx.y * 128;

    extern __shared__ char smraw[];
    const uint32_t su = smem_u32(smraw);

    const int tid  = threadIdx.x;
    const int wid  = tid >> 5;
    const int lane = tid & 31;
    const int g    = lane >> 2;
    const int tg   = lane & 3;
    const int wr   = wid & 1;
    const int wc   = wid >> 1;

    const __half* Asrc = (GELU_OUT ? g_Xgh : g_Hh) + (size_t)(base + m0) * KDIM;
    const __half* Bsrc = Bmat + (size_t)e * KDIM * NDIM + n0;

    const int am = tid >> 1;
    const int ac = (tid & 1) * 2;
    const int bk = tid >> 3;
    const int bc = (tid & 7) * 2;

    const int lane_r  = (lane & 7) + ((lane >> 3) & 1) * 8;
    const int lane_k8 = (lane >> 4) * 16;

    float c[4][4][4];
    #pragma unroll
    for (int i = 0; i < 4; i++)
        #pragma unroll
        for (int j = 0; j < 4; j++)
            #pragma unroll
            for (int k = 0; k < 4; k++) c[i][j][k] = 0.f;

    const int KC = KDIM / 32;

    #define LOAD_TILES(kc_, buf_) do { \
        uint32_t sa = su + (buf_) * BUFB; \
        uint32_t sb = sa + ABUFB; \
        const __half* asp = Asrc + (size_t)am * KDIM + (kc_) * 32; \
        _Pragma("unroll") \
        for (int j = 0; j < 2; j++) \
            CP_ASYNC16(sa + (uint32_t)(am * 80 + (ac + j) * 16), asp + (ac + j) * 8); \
        const __half* bsp = Bsrc + (size_t)((kc_) * 32 + bk) * NDIM; \
        _Pragma("unroll") \
        for (int j = 0; j < 2; j++) \
            CP_ASYNC16(sb + (uint32_t)(bk * 272 + (bc + j) * 16), bsp + (bc + j) * 8); \
    } while (0)

    LOAD_TILES(0, 0); CP_COMMIT();
    LOAD_TILES(1, 1); CP_COMMIT();
    LOAD_TILES(2, 2); CP_COMMIT();

    for (int kc = 0; kc < KC; kc++) {
        CP_WAIT2();
        __syncthreads();
        if (kc + 3 < KC) LOAD_TILES(kc + 3, (kc + 3) & 3);
        CP_COMMIT();

        const uint32_t sa = su + (kc & 3) * BUFB;
        const uint32_t sb = sa + ABUFB;
        const uint32_t a_base = sa + (uint32_t)((wr * 64 + lane_r) * 80) + lane_k8;
        const uint32_t b_base = sb + (uint32_t)(lane_r * 272 + wc * 64) + lane_k8;

        #pragma unroll
        for (int ks = 0; ks < 2; ks++) {
            uint32_t a[4][4];
            #pragma unroll
            for (int mf = 0; mf < 4; mf++)
                LDMATRIX_X4(a[mf][0], a[mf][1], a[mf][2], a[mf][3],
                            a_base + mf * 1280 + ks * 32);
            uint32_t b[4][2];
            #pragma unroll
            for (int np = 0; np < 2; np++) {
                uint32_t r0, r1, r2, r3;
                LDMATRIX_X4_T(r0, r1, r2, r3, b_base + ks * 4352 + np * 32);
                b[np * 2 + 0][0] = r0; b[np * 2 + 0][1] = r1;
                b[np * 2 + 1][0] = r2; b[np * 2 + 1][1] = r3;
            }
            #pragma unroll
            for (int mf = 0; mf < 4; mf++)
                #pragma unroll
                for (int nf = 0; nf < 4; nf++)
                    MMA_F16(c[mf][nf], a[mf], b[nf][0], b[nf][1]);
        }
    }

    // -------- epilogue --------
    #pragma unroll
    for (int mf = 0; mf < 4; mf++) {
        #pragma unroll
        for (int half_ = 0; half_ < 2; half_++) {
            int rl = wr * 64 + mf * 16 + g + half_ * 8;
            int m = m0 + rl;
            if (m >= count) continue;
            if (GELU_OUT) {
                __half* hrow = g_Hh + (size_t)(base + m) * FFN_;
                #pragma unroll
                for (int nf = 0; nf < 4; nf++) {
                    int col = n0 + wc * 32 + nf * 8 + 2 * tg;
                    float2 bb = *(const float2*)(bias + (size_t)e * NDIM + col);
                    __half2 hv = __floats2half2_rn(
                        gelu_exact(c[mf][nf][half_ * 2 + 0] + bb.x),
                        gelu_exact(c[mf][nf][half_ * 2 + 1] + bb.y));
                    *reinterpret_cast<__half2*>(hrow + col) = hv;
                }
            } else {
                int tok = g_tok[e][m];
                float gt = g_gate[e][m];
                float* orow = outp + (size_t)tok * DM;
                #pragma unroll
                for (int nf = 0; nf < 4; nf++) {
                    int col = n0 + wc * 32 + nf * 8 + 2 * tg;
                    float2 bb = *(const float2*)(bias + (size_t)e * NDIM + col);
                    atomicAdd(orow + col + 0, gt * (c[mf][nf][half_ * 2 + 0] + bb.x));
                    atomicAdd(orow + col + 1, gt * (c[mf][nf][half_ * 2 + 1] + bb.y));
                }
            }
        }
    }
}

// ---------------- launch ----------------
extern "C" void kernel_launch(void* const* d_in, const int* in_sizes, int n_in,
                              void* d_out, int out_size) {
    const float* x  = (const float*)d_in[0];
    const float* gw = (const float*)d_in[1];
    const float* gb = (const float*)d_in[2];
    const float* w1 = (const float*)d_in[3];
    const float* b1 = (const float*)d_in[4];
    const float* w2 = (const float*)d_in[5];
    const float* b2 = (const float*)d_in[6];
    float* out = (float*)d_out;
    const int T = in_sizes[0] / DM;

    __half* w1h; cudaGetSymbolAddress((void**)&w1h, g_w1h);
    __half* w2h; cudaGetSymbolAddress((void**)&w2h, g_w2h);

    static cudaStream_t s1 = nullptr;
    static cudaEvent_t evRoot = nullptr, evW1 = nullptr, evW2 = nullptr;
    static int once = 0;
    if (!once) {
        cudaStreamCreateWithFlags(&s1, cudaStreamNonBlocking);
        cudaEventCreateWithFlags(&evRoot, cudaEventDisableTiming);
        cudaEventCreateWithFlags(&evW1, cudaEventDisableTiming);
        cudaEventCreateWithFlags(&evW2, cudaEventDisableTiming);
        cudaFuncSetAttribute(gemm_mma<DM, FFN_, true>,
                             cudaFuncAttributeMaxDynamicSharedMemorySize, SMEM_DYN);
        cudaFuncSetAttribute(gemm_mma<FFN_, DM, false>,
                             cudaFuncAttributeMaxDynamicSharedMemorySize, SMEM_DYN);
        once = 1;
    }

    const int n8 = NE * DM * FFN_ / 8;

    // fork: weight conversion on side stream s1
    cudaEventRecord(evRoot, 0);
    cudaStreamWaitEvent(s1, evRoot, 0);
    conv_half_kernel<<<(n8 + 255) / 256, 256, 0, s1>>>((const float4*)w1, (uint4*)w1h, n8);
    cudaEventRecord(evW1, s1);
    conv_half_kernel<<<(n8 + 255) / 256, 256, 0, s1>>>((const float4*)w2, (uint4*)w2h, n8);
    cudaEventRecord(evW2, s1);

    // main stream: routing + gather + memset
    init_kernel<<<1, 32>>>();
    route_kernel<<<(T + 7) / 8, 256>>>(x, gw, gb, T);
    base_kernel<<<1, 32>>>();
    gather_kernel<<<dim3((T + 1) / 2, NE), 256>>>(x);
    cudaMemsetAsync(d_out, 0, (size_t)out_size * sizeof(float), 0);

    // join w1, run GEMM1 (conv w2 overlaps on s1)
    cudaStreamWaitEvent(0, evW1, 0);
    gemm_mma<DM, FFN_, true><<<dim3(T / 128, FFN_ / 128, NE), 256, SMEM_DYN>>>(w1h, b1, nullptr);

    // join w2, run GEMM2
    cudaStreamWaitEvent(0, evW2, 0);
    gemm_mma<FFN_, DM, false><<<dim3(T / 128, DM / 128, NE), 256, SMEM_DYN>>>(w2h, b2, out);
}

// round 14
// speedup vs baseline: 1.5338x; 1.0015x over previous
#include <cuda_runtime.h>
#include <cuda_fp16.h>
#include <math.h>
#include <stdint.h>

#define DM    1024
#define FFN_  4096
#define NE    8
#define TMAX  8192

// ---------------- device scratch (static per-expert capacity layout) ----------------
__device__ int    g_counts[NE];
__device__ int    g_tok[NE][TMAX];
__device__ float  g_gate[NE][TMAX];
__device__ __half g_Xgh[(size_t)NE * TMAX * DM];    // row = e*TMAX + slot
__device__ __half g_Hh[(size_t)NE * TMAX * FFN_];   // row = e*TMAX + slot
__device__ __half g_w1h[(size_t)NE * DM * FFN_];
__device__ __half g_w2h[(size_t)NE * FFN_ * DM];

// ---------------- helpers ----------------
__device__ __forceinline__ uint32_t smem_u32(const void* p) {
    uint32_t a;
    asm("{ .reg .u64 t; cvta.to.shared.u64 t, %1; cvt.u32.u64 %0, t; }" : "=r"(a) : "l"(p));
    return a;
}
__device__ __forceinline__ float gelu_exact(float v) {
    return 0.5f * v * (1.f + erff(v * 0.7071067811865476f));
}

#define CP_ASYNC16(dst, src) \
    asm volatile("cp.async.cg.shared.global [%0], [%1], 16;" :: "r"(dst), "l"(src) : "memory")
#define CP_COMMIT()  asm volatile("cp.async.commit_group;" ::: "memory")
#define CP_WAIT2()   asm volatile("cp.async.wait_group 2;" ::: "memory")

#define LDMATRIX_X4(r0,r1,r2,r3, addr) \
    asm volatile("ldmatrix.sync.aligned.m8n8.x4.shared.b16 {%0,%1,%2,%3}, [%4];" \
        : "=r"(r0), "=r"(r1), "=r"(r2), "=r"(r3) : "r"(addr))
#define LDMATRIX_X4_T(r0,r1,r2,r3, addr) \
    asm volatile("ldmatrix.sync.aligned.m8n8.x4.trans.shared.b16 {%0,%1,%2,%3}, [%4];" \
        : "=r"(r0), "=r"(r1), "=r"(r2), "=r"(r3) : "r"(addr))

#define MMA_F16(c, a, b0, b1) \
    asm volatile("mma.sync.aligned.m16n8k16.row.col.f32.f16.f16.f32 " \
        "{%0,%1,%2,%3}, {%4,%5,%6,%7}, {%8,%9}, {%0,%1,%2,%3};" \
        : "+f"((c)[0]), "+f"((c)[1]), "+f"((c)[2]), "+f"((c)[3]) \
        : "r"((a)[0]), "r"((a)[1]), "r"((a)[2]), "r"((a)[3]), "r"(b0), "r"(b1))

// ---------------- routing (fused with gather) ----------------
__global__ void init_kernel() { if (threadIdx.x < NE) g_counts[threadIdx.x] = 0; }

__global__ void route_gather_kernel(const float* __restrict__ x,
                                    const float* __restrict__ gw,
                                    const float* __restrict__ gb, int T) {
    int warp = (blockIdx.x * blockDim.x + threadIdx.x) >> 5;
    int lane = threadIdx.x & 31;
    if (warp >= T) return;
    const float* xr = x + (size_t)warp * DM;
    float acc[NE];
    #pragma unroll
    for (int e = 0; e < NE; e++) acc[e] = 0.f;
    for (int d = lane; d < DM; d += 32) {
        float xv = xr[d];
        const float4* g4 = (const float4*)(gw + (size_t)d * NE);
        float4 a = g4[0], b = g4[1];
        acc[0] += xv*a.x; acc[1] += xv*a.y; acc[2] += xv*a.z; acc[3] += xv*a.w;
        acc[4] += xv*b.x; acc[5] += xv*b.y; acc[6] += xv*b.z; acc[7] += xv*b.w;
    }
    #pragma unroll
    for (int e = 0; e < NE; e++)
        #pragma unroll
        for (int o = 16; o > 0; o >>= 1) acc[e] += __shfl_xor_sync(0xFFFFFFFFu, acc[e], o);

    int i1 = 0, i2 = 0, s1 = 0, s2 = 0;
    if (lane == 0) {
        float v[NE];
        #pragma unroll
        for (int e = 0; e < NE; e++) v[e] = acc[e] + gb[e];
        i1 = 0;
        #pragma unroll
        for (int e = 1; e < NE; e++) if (v[e] > v[i1]) i1 = e;
        i2 = (i1 == 0) ? 1 : 0;
        #pragma unroll
        for (int e = 0; e < NE; e++) if (e != i1 && v[e] > v[i2]) i2 = e;
        float e2 = expf(v[i2] - v[i1]);
        float s = 1.f + e2;
        s1 = atomicAdd(&g_counts[i1], 1);
        g_tok[i1][s1] = warp; g_gate[i1][s1] = 1.f / s;
        s2 = atomicAdd(&g_counts[i2], 1);
        g_tok[i2][s2] = warp; g_gate[i2][s2] = e2 / s;
    }
    i1 = __shfl_sync(0xFFFFFFFFu, i1, 0);
    i2 = __shfl_sync(0xFFFFFFFFu, i2, 0);
    s1 = __shfl_sync(0xFFFFFFFFu, s1, 0);
    s2 = __shfl_sync(0xFFFFFFFFu, s2, 0);

    // fused gather: copy token row (fp16) to both expert slots
    const float4* src = (const float4*)xr;
    uint2* d1 = (uint2*)(g_Xgh + ((size_t)i1 * TMAX + s1) * DM);
    uint2* d2 = (uint2*)(g_Xgh + ((size_t)i2 * TMAX + s2) * DM);
    #pragma unroll
    for (int j = 0; j < 8; j++) {
        int idx = lane + j * 32;
        float4 v = src[idx];
        __half2 h0 = __floats2half2_rn(v.x, v.y);
        __half2 h1 = __floats2half2_rn(v.z, v.w);
        uint2 o;
        o.x = *reinterpret_cast<uint32_t*>(&h0);
        o.y = *reinterpret_cast<uint32_t*>(&h1);
        d1[idx] = o;
        d2[idx] = o;
    }
}

// fp32 -> fp16 weight conversion (8 floats / thread, 16B store)
__global__ void conv_half_kernel(const float4* __restrict__ src, uint4* __restrict__ dst, int n8) {
    int i = blockIdx.x * blockDim.x + threadIdx.x;
    if (i >= n8) return;
    float4 v0 = src[i * 2], v1 = src[i * 2 + 1];
    __half2 h0 = __floats2half2_rn(v0.x, v0.y);
    __half2 h1 = __floats2half2_rn(v0.z, v0.w);
    __half2 h2 = __floats2half2_rn(v1.x, v1.y);
    __half2 h3 = __floats2half2_rn(v1.z, v1.w);
    uint4 o;
    o.x = *reinterpret_cast<uint32_t*>(&h0);
    o.y = *reinterpret_cast<uint32_t*>(&h1);
    o.z = *reinterpret_cast<uint32_t*>(&h2);
    o.w = *reinterpret_cast<uint32_t*>(&h3);
    dst[i] = o;
}

// ---------------- fp16 mma grouped GEMM (R5 config, static bases) ----------------
#define ASTRH 40
#define BSTRH 136
#define ABUFB (128 * ASTRH * 2)
#define BBUFB (32 * BSTRH * 2)
#define BUFB  (ABUFB + BBUFB)
#define NSTAGE 4
#define SMEM_DYN (NSTAGE * BUFB)

template<int KDIM, int NDIM, bool GELU_OUT>
__global__ void __launch_bounds__(256, 2)
gemm_mma(const __half* __restrict__ Bmat, const float* __restrict__ bias,
         float* __restrict__ outp) {
    const int e = blockIdx.z;
    const int count = g_counts[e];
    const int m0 = blockIdx.x * 128;
    if (m0 >= count) return;
    const size_t base = (size_t)e * TMAX;
    const int n0 = blockIdx.y * 128;

    extern __shared__ char smraw[];
    const uint32_t su = smem_u32(smraw);

    const int tid  = threadIdx.x;
    const int wid  = tid >> 5;
    const int lane = tid & 31;
    const int g    = lane >> 2;
    const int tg   = lane & 3;
    const int wr   = wid & 1;
    const int wc   = wid >> 1;

    const __half* Asrc = (GELU_OUT ? g_Xgh : g_Hh) + (base + m0) * KDIM;
    const __half* Bsrc = Bmat + (size_t)e * KDIM * NDIM + n0;

    const int am = tid >> 1;
    const int ac = (tid & 1) * 2;
    const int bk = tid >> 3;
    const int bc = (tid & 7) * 2;

    const int lane_r  = (lane & 7) + ((lane >> 3) & 1) * 8;
    const int lane_k8 = (lane >> 4) * 16;

    float c[4][4][4];
    #pragma unroll
    for (int i = 0; i < 4; i++)
        #pragma unroll
        for (int j = 0; j < 4; j++)
            #pragma unroll
            for (int k = 0; k < 4; k++) c[i][j][k] = 0.f;

    const int KC = KDIM / 32;

    #define LOAD_TILES(kc_, buf_) do { \
        uint32_t sa = su + (buf_) * BUFB; \
        uint32_t sb = sa + ABUFB; \
        const __half* asp = Asrc + (size_t)am * KDIM + (kc_) * 32; \
        _Pragma("unroll") \
        for (int j = 0; j < 2; j++) \
            CP_ASYNC16(sa + (uint32_t)(am * 80 + (ac + j) * 16), asp + (ac + j) * 8); \
        const __half* bsp = Bsrc + (size_t)((kc_) * 32 + bk) * NDIM; \
        _Pragma("unroll") \
        for (int j = 0; j < 2; j++) \
            CP_ASYNC16(sb + (uint32_t)(bk * 272 + (bc + j) * 16), bsp + (bc + j) * 8); \
    } while (0)

    LOAD_TILES(0, 0); CP_COMMIT();
    LOAD_TILES(1, 1); CP_COMMIT();
    LOAD_TILES(2, 2); CP_COMMIT();

    for (int kc = 0; kc < KC; kc++) {
        CP_WAIT2();
        __syncthreads();
        if (kc + 3 < KC) LOAD_TILES(kc + 3, (kc + 3) & 3);
        CP_COMMIT();

        const uint32_t sa = su + (kc & 3) * BUFB;
        const uint32_t sb = sa + ABUFB;
        const uint32_t a_base = sa + (uint32_t)((wr * 64 + lane_r) * 80) + lane_k8;
        const uint32_t b_base = sb + (uint32_t)(lane_r * 272 + wc * 64) + lane_k8;

        #pragma unroll
        for (int ks = 0; ks < 2; ks++) {
            uint32_t a[4][4];
            #pragma unroll
            for (int mf = 0; mf < 4; mf++)
                LDMATRIX_X4(a[mf][0], a[mf][1], a[mf][2], a[mf][3],
                            a_base + mf * 1280 + ks * 32);
            uint32_t b[4][2];
            #pragma unroll
            for (int np = 0; np < 2; np++) {
                uint32_t r0, r1, r2, r3;
                LDMATRIX_X4_T(r0, r1, r2, r3, b_base + ks * 4352 + np * 32);
                b[np * 2 + 0][0] = r0; b[np * 2 + 0][1] = r1;
                b[np * 2 + 1][0] = r2; b[np * 2 + 1][1] = r3;
            }
            #pragma unroll
            for (int mf = 0; mf < 4; mf++)
                #pragma unroll
                for (int nf = 0; nf < 4; nf++)
                    MMA_F16(c[mf][nf], a[mf], b[nf][0], b[nf][1]);
        }
    }

    // -------- epilogue --------
    #pragma unroll
    for (int mf = 0; mf < 4; mf++) {
        #pragma unroll
        for (int half_ = 0; half_ < 2; half_++) {
            int rl = wr * 64 + mf * 16 + g + half_ * 8;
            int m = m0 + rl;
            if (m >= count) continue;
            if (GELU_OUT) {
                __half* hrow = g_Hh + (base + m) * FFN_;
                #pragma unroll
                for (int nf = 0; nf < 4; nf++) {
                    int col = n0 + wc * 32 + nf * 8 + 2 * tg;
                    float2 bb = *(const float2*)(bias + (size_t)e * NDIM + col);
                    __half2 hv = __floats2half2_rn(
                        gelu_exact(c[mf][nf][half_ * 2 + 0] + bb.x),
                        gelu_exact(c[mf][nf][half_ * 2 + 1] + bb.y));
                    *reinterpret_cast<__half2*>(hrow + col) = hv;
                }
            } else {
                int tok = g_tok[e][m];
                float gt = g_gate[e][m];
                float* orow = outp + (size_t)tok * DM;
                #pragma unroll
                for (int nf = 0; nf < 4; nf++) {
                    int col = n0 + wc * 32 + nf * 8 + 2 * tg;
                    float2 bb = *(const float2*)(bias + (size_t)e * NDIM + col);
                    atomicAdd(orow + col + 0, gt * (c[mf][nf][half_ * 2 + 0] + bb.x));
                    atomicAdd(orow + col + 1, gt * (c[mf][nf][half_ * 2 + 1] + bb.y));
                }
            }
        }
    }
}

// ---------------- launch ----------------
extern "C" void kernel_launch(void* const* d_in, const int* in_sizes, int n_in,
                              void* d_out, int out_size) {
    const float* x  = (const float*)d_in[0];
    const float* gw = (const float*)d_in[1];
    const float* gb = (const float*)d_in[2];
    const float* w1 = (const float*)d_in[3];
    const float* b1 = (const float*)d_in[4];
    const float* w2 = (const float*)d_in[5];
    const float* b2 = (const float*)d_in[6];
    float* out = (float*)d_out;
    const int T = in_sizes[0] / DM;

    __half* w1h; cudaGetSymbolAddress((void**)&w1h, g_w1h);
    __half* w2h; cudaGetSymbolAddress((void**)&w2h, g_w2h);

    static cudaStream_t s1 = nullptr;
    static cudaEvent_t evRoot = nullptr, evW1 = nullptr, evW2 = nullptr;
    static int once = 0;
    if (!once) {
        cudaStreamCreateWithFlags(&s1, cudaStreamNonBlocking);
        cudaEventCreateWithFlags(&evRoot, cudaEventDisableTiming);
        cudaEventCreateWithFlags(&evW1, cudaEventDisableTiming);
        cudaEventCreateWithFlags(&evW2, cudaEventDisableTiming);
        cudaFuncSetAttribute(gemm_mma<DM, FFN_, true>,
                             cudaFuncAttributeMaxDynamicSharedMemorySize, SMEM_DYN);
        cudaFuncSetAttribute(gemm_mma<FFN_, DM, false>,
                             cudaFuncAttributeMaxDynamicSharedMemorySize, SMEM_DYN);
        once = 1;
    }

    const int n8 = NE * DM * FFN_ / 8;

    // fork: weight conversion + out memset on side stream s1
    cudaEventRecord(evRoot, 0);
    cudaStreamWaitEvent(s1, evRoot, 0);
    conv_half_kernel<<<(n8 + 255) / 256, 256, 0, s1>>>((const float4*)w1, (uint4*)w1h, n8);
    cudaEventRecord(evW1, s1);
    cudaMemsetAsync(d_out, 0, (size_t)out_size * sizeof(float), s1);
    conv_half_kernel<<<(n8 + 255) / 256, 256, 0, s1>>>((const float4*)w2, (uint4*)w2h, n8);
    cudaEventRecord(evW2, s1);

    // main stream: routing (fused gather)
    init_kernel<<<1, 32>>>();
    route_gather_kernel<<<(T + 7) / 8, 256>>>(x, gw, gb, T);

    // join w1, run GEMM1 (conv w2 + memset overlap on s1)
    cudaStreamWaitEvent(0, evW1, 0);
    gemm_mma<DM, FFN_, true><<<dim3(T / 128, FFN_ / 128, NE), 256, SMEM_DYN>>>(w1h, b1, nullptr);

    // join w2 (+memset), run GEMM2
    cudaStreamWaitEvent(0, evW2, 0);
    gemm_mma<FFN_, DM, false><<<dim3(T / 128, DM / 128, NE), 256, SMEM_DYN>>>(w2h, b2, out);
}